// round 17
// baseline (speedup 1.0000x reference)
#include <cuda_runtime.h>
#include <cuda.h>
#include <stdint.h>

// Depthwise 3x3 conv (256 ch x 2 filters) fused with butterfly wing-swap add.
//   out[c]  = conv(x[c],  w[2c])   + conv(x[cp], w[2cp+1])
//   out[cp] = conv(x[cp], w[2cp])  + conv(x[c],  w[2c+1]),  cp = c+4 within butterfly
// R17: TMA (cp.async.bulk.tensor.4d) fills BOTH channel planes of a half-tile
// with ONE instruction (box {56,30,1,2}; OOB rows hardware zero-filled), into
// dense ST=56 smem. Compute: 7-col strips x 4-row groups (provably conflict-free
// at ST=56), streaming packed fma.rn.f32x2. Double-buffered mbarrier pipeline.

#define CH 256
#define HW 56
#define PLANE (HW * HW)
#define SLOTS 30                 // input rows h0-1 .. h0+28
#define STW 56                   // words per smem row (dense TMA box)
#define CPLANE (SLOTS * STW)     // 1680 words per channel plane
#define TILEW (2 * CPLANE)       // 3360 words per buffer
#define TILEB (TILEW * 4)        // 13440 bytes
#define NTHREADS 224
#define NTILES 8192              // 32 batch * 128 pairs * 2 halves
#define GRID 608                 // 4 blocks/SM * 152 SMs

typedef unsigned long long ull;

__device__ __forceinline__ ull fma2(ull a, ull b, ull c) {
    ull d; asm("fma.rn.f32x2 %0, %1, %2, %3;" : "=l"(d) : "l"(a), "l"(b), "l"(c)); return d;
}
__device__ __forceinline__ ull pack2(float lo, float hi) {
    ull r; asm("mov.b64 %0, {%1, %2};" : "=l"(r) : "f"(lo), "f"(hi)); return r;
}
__device__ __forceinline__ float2 unpack2(ull v) {
    float2 r; asm("mov.b64 {%0, %1}, %2;" : "=f"(r.x), "=f"(r.y) : "l"(v)); return r;
}
__device__ __forceinline__ void wait_parity(uint32_t mb, uint32_t ph) {
    asm volatile(
        "{\n\t.reg .pred P;\n"
        "WL_%=:\n\t"
        "mbarrier.try_wait.parity.acquire.cta.shared::cta.b64 P, [%0], %1, 0x989680;\n\t"
        "@P bra.uni WD_%=;\n\t"
        "bra.uni WL_%=;\n\t"
        "WD_%=:\n\t}"
        :: "r"(mb), "r"(ph) : "memory");
}

__global__ __launch_bounds__(NTHREADS, 4)
void conv_butterfly_kernel(const __grid_constant__ CUtensorMap tmap,
                           const float* __restrict__ w,
                           float* __restrict__ out)
{
    extern __shared__ float smraw[];
    __shared__ __align__(16) ull wsm[18];      // per-dr: Wc0,Wc1,Wc2,Wp0,Wp1,Wp2
    __shared__ __align__(8) ull mbar[2];

    float* sbuf = (float*)(((uintptr_t)smraw + 127) & ~(uintptr_t)127);
    const uint32_t sbase = (uint32_t)__cvta_generic_to_shared(sbuf);
    const uint32_t mb0 = (uint32_t)__cvta_generic_to_shared(&mbar[0]);
    const uint32_t mb1 = (uint32_t)__cvta_generic_to_shared(&mbar[1]);

    const int tid    = threadIdx.x;
    const int warpid = tid >> 5;               // 0..6
    const int lane   = tid & 31;
    const int lr     = lane >> 3;              // row in group 0..3
    const int lc     = lane & 7;               // 7-col strip 0..7

    if (tid == 0) {
        asm volatile("mbarrier.init.shared.b64 [%0], 1;" :: "r"(mb0));
        asm volatile("mbarrier.init.shared.b64 [%0], 1;" :: "r"(mb1));
        asm volatile("fence.proxy.async.shared::cta;" ::: "memory");
    }
    __syncthreads();

    // one 4D TMA load fills both channel planes of half-tile t into buffer b
    auto issue_tma = [&](int t, int b, uint32_t mb) {
        const int half = t & 1, p = (t >> 1) & 127, n = t >> 8;
        const int h0 = half * 28;
        const int j  = p & 3;                  // wing slot
        const int qc = n * 64 + 2 * (p >> 2);  // (channel>>2) global index
        asm volatile("mbarrier.arrive.expect_tx.shared.b64 _, [%0], %1;"
                     :: "r"(mb), "r"((uint32_t)TILEB) : "memory");
        asm volatile(
            "cp.async.bulk.tensor.4d.shared::cta.global.tile.mbarrier::complete_tx::bytes "
            "[%0], [%1, {%2, %3, %4, %5}], [%6];"
            :: "r"(sbase + (uint32_t)(b * TILEB)), "l"(&tmap),
               "r"(0), "r"(h0 - 1), "r"(j), "r"(qc), "r"(mb) : "memory");
    };

    int t = blockIdx.x;
    int b = 0;
    uint32_t ph0 = 0, ph1 = 0;
    if (tid == 0) issue_tma(t, 0, mb0);

    while (t < NTILES) {
        const int tn = t + GRID;
        if (tid == 0 && tn < NTILES) {
            asm volatile("fence.proxy.async.shared::cta;" ::: "memory");
            issue_tma(tn, b ^ 1, (b ^ 1) ? mb1 : mb0);
        }

        const int half = t & 1, p = (t >> 1) & 127, n = t >> 8;
        const int c  = ((p >> 2) << 3) + (p & 3);
        const int h0 = half * 28;

        // stage packed weights (18 threads, one ull each)
        if (tid < 18) {
            const float* wa = w + 18 * c;         // [w2c | w2c+1]
            const float* wb = w + 18 * (c + 4);   // [w2cp | w2cp+1]
            const int dr = tid / 6, sl = tid % 6;
            ull v;
            if (sl < 3) { const int k = dr * 3 + sl;     v = pack2(__ldg(wa + k),     __ldg(wb + 9 + k)); }
            else        { const int k = dr * 3 + sl - 3; v = pack2(__ldg(wa + 9 + k), __ldg(wb + k)); }
            wsm[tid] = v;
        }

        // wait for this tile's TMA (issued last iteration / prologue)
        wait_parity(b ? mb1 : mb0, b ? ph1 : ph0);
        if (b) ph1 ^= 1; else ph0 ^= 1;
        __syncthreads();                          // wsm visible; all past wait

        const float* p0 = sbuf + b * TILEW;       // ch c plane
        const int r  = (warpid << 2) + lr;        // local output row 0..27
        const int c0 = lc * 7;                    // output col base 0..49

        ull A[7], Q[7];
        #pragma unroll
        for (int o = 0; o < 7; o++) { A[o] = 0ull; Q[o] = 0ull; }

        #pragma unroll
        for (int dr = 0; dr < 3; dr++) {
            const float* r0 = p0 + (r + dr) * STW + c0;   // input row h0+r-1+dr
            const float* r1 = r0 + CPLANE;                // ch c+4
            const ulonglong2 wA = *(const ulonglong2*)(wsm + dr * 6);
            const ulonglong2 wB = *(const ulonglong2*)(wsm + dr * 6 + 2);
            const ulonglong2 wC = *(const ulonglong2*)(wsm + dr * 6 + 4);
            const ull wc0 = wA.x, wc1 = wA.y, wc2 = wB.x;
            const ull wp0 = wB.y, wp1 = wC.x, wp2 = wC.y;
            ull v;
            {   // input word c0-1 (left halo; plane edge -> 0)
                const float e = (lc == 0) ? 0.f : r0[-1];
                const float f = (lc == 0) ? 0.f : r1[-1];
                v = pack2(e, f);
                A[0] = fma2(v, wc0, A[0]); Q[0] = fma2(v, wp0, Q[0]);
            }
            #pragma unroll
            for (int j = 0; j < 7; j++) {         // input words c0..c0+6
                v = pack2(r0[j], r1[j]);
                if (j < 6) { A[j+1] = fma2(v, wc0, A[j+1]); Q[j+1] = fma2(v, wp0, Q[j+1]); }
                A[j] = fma2(v, wc1, A[j]); Q[j] = fma2(v, wp1, Q[j]);
                if (j > 0) { A[j-1] = fma2(v, wc2, A[j-1]); Q[j-1] = fma2(v, wp2, Q[j-1]); }
            }
            {   // input word c0+7 (right halo; plane edge -> 0)
                const float e = (lc == 7) ? 0.f : r0[7];
                const float f = (lc == 7) ? 0.f : r1[7];
                v = pack2(e, f);
                A[6] = fma2(v, wc2, A[6]); Q[6] = fma2(v, wp2, Q[6]);
            }
        }

        float* o0 = out + ((size_t)n * CH + c) * PLANE + (size_t)(h0 + r) * HW + c0;
        float* o1 = o0 + 4 * PLANE;
        #pragma unroll
        for (int o = 0; o < 7; o++) {
            const float2 ua = unpack2(A[o]); o0[o] = ua.x + ua.y;
            const float2 uq = unpack2(Q[o]); o1[o] = uq.x + uq.y;
        }

        __syncthreads();       // all reads of buffer b done before next TMA into it
        t = tn;
        b ^= 1;
    }
}

extern "C" void kernel_launch(void* const* d_in, const int* in_sizes, int n_in,
                              void* d_out, int out_size)
{
    const float* x = (const float*)d_in[0];
    const float* w = (const float*)d_in[1];
    float* out = (float*)d_out;
    (void)in_sizes; (void)n_in; (void)out_size;

    // Encode tensor map host-side via runtime-queried driver entry point (no -lcuda).
    typedef CUresult (*EncFn)(CUtensorMap*, CUtensorMapDataType, cuuint32_t, void*,
                              const cuuint64_t*, const cuuint64_t*, const cuuint32_t*,
                              const cuuint32_t*, CUtensorMapInterleave, CUtensorMapSwizzle,
                              CUtensorMapL2promotion, CUtensorMapFloatOOBfill);
    void* fp = nullptr;
    cudaDriverEntryPointQueryResult qr;
    cudaGetDriverEntryPointByVersion("cuTensorMapEncodeTiled", &fp, 12000,
                                     cudaEnableDefault, &qr);
    EncFn enc = (EncFn)fp;

    CUtensorMap tmap;
    // x viewed as [q=2048][j=4][row=56][col=56] f32, q = (n*256+ch)>>2, j = ch&3.
    // Butterfly partners c, c+4 are adjacent in q -> one box {56,30,1,2} covers both.
    cuuint64_t dims[4]    = {56, 56, 4, 2048};
    cuuint64_t strides[3] = {HW * 4ull, (cuuint64_t)PLANE * 4ull, (cuuint64_t)PLANE * 16ull};
    cuuint32_t box[4]     = {56, 30, 1, 2};
    cuuint32_t es[4]      = {1, 1, 1, 1};
    enc(&tmap, CU_TENSOR_MAP_DATA_TYPE_FLOAT32, 4, (void*)x, dims, strides, box, es,
        CU_TENSOR_MAP_INTERLEAVE_NONE, CU_TENSOR_MAP_SWIZZLE_NONE,
        CU_TENSOR_MAP_L2_PROMOTION_L2_128B, CU_TENSOR_MAP_FLOAT_OOB_FILL_NONE);

    const int smem_bytes = 2 * TILEB + 256;     // two buffers + alignment slack
    conv_butterfly_kernel<<<GRID, NTHREADS, smem_bytes>>>(tmap, w, out);
}